// round 15
// baseline (speedup 1.0000x reference)
#include <cuda_runtime.h>
#include <cuda_bf16.h>
#include <cuda_fp16.h>
#include <cstdint>
#include <math.h>

#define NTOT   8192
#define BHALF  4096
#define DDIM   256
#define NBLK   64                 // 128-row blocks
#define TILEB  65536              // 128 rows * 512 B (bf16)
#define SMEM_TOTAL (3 * TILEB)    // A + B0 + B1 = 192 KB

// ---------------- scratch (device globals; allocation-free) ----------------
__device__ __align__(16) __nv_bfloat16 g_znb[NTOT * DDIM]; // bf16 * sqrt(10*log2 e)
__device__ __align__(16) float g_part[NBLK * NTOT]; // [slot][row] exp2 partials
__device__ float  g_pos[BHALF];          // ln-domain positive-pair sims
__device__ float2 g_red[16];             // per-finalize-block (sum, cnt)
__device__ int    g_count;               // finalize completion counter

// ---------------- helpers (baseline PTX only) ----------------
__device__ __forceinline__ uint32_t s2u(const void* p) {
    return (uint32_t)__cvta_generic_to_shared(p);
}
__device__ __forceinline__ void cp16(uint32_t dst, const void* src) {
    asm volatile("cp.async.cg.shared.global [%0], [%1], 16;"
                 :: "r"(dst), "l"(src) : "memory");
}
__device__ __forceinline__ void cp_commit() {
    asm volatile("cp.async.commit_group;" ::: "memory");
}
template <int N> __device__ __forceinline__ void cp_wait() {
    asm volatile("cp.async.wait_group %0;" :: "n"(N) : "memory");
}
__device__ __forceinline__ float ex2(float x) {
    float r;
    asm("ex2.approx.ftz.f32 %0, %1;" : "=f"(r) : "f"(x));
    return r;
}
// pack two f32 into f16x2 (lo = a, hi = b)
__device__ __forceinline__ uint32_t pack_h2(float a, float b) {
    uint32_t r;
    asm("cvt.rn.f16x2.f32 %0, %1, %2;" : "=r"(r) : "f"(b), "f"(a));
    return r;
}
__device__ __forceinline__ uint32_t ex2_h2(uint32_t x) {
    uint32_t r;
    asm("ex2.approx.f16x2 %0, %1;" : "=r"(r) : "r"(x));
    return r;
}
__device__ __forceinline__ void hadd2(uint32_t& acc, uint32_t v) {
    asm("add.rn.f16x2 %0, %0, %1;" : "+r"(acc) : "r"(v));
}
#define LDSM4(r0, r1, r2, r3, addr)                                           \
    asm volatile("ldmatrix.sync.aligned.m8n8.x4.shared.b16 {%0,%1,%2,%3}, [%4];" \
                 : "=r"(r0), "=r"(r1), "=r"(r2), "=r"(r3) : "r"(addr))
#define MMA16816(d, a, b)                                                     \
    asm volatile("mma.sync.aligned.m16n8k16.row.col.f32.bf16.bf16.f32 "       \
                 "{%0,%1,%2,%3},{%4,%5,%6,%7},{%8,%9},{%0,%1,%2,%3};"         \
                 : "+f"((d)[0]), "+f"((d)[1]), "+f"((d)[2]), "+f"((d)[3])     \
                 : "r"((a)[0]), "r"((a)[1]), "r"((a)[2]), "r"((a)[3]),        \
                   "r"((b)[0]), "r"((b)[1]))

// 16B-unit XOR swizzle within a 512B row (32 units/row)
__device__ __forceinline__ uint32_t sw_off(int row, int u) {
    return (uint32_t)((row * 32 + (u ^ (row & 7))) << 4);
}

// Load a 128-row x 512-byte block (64 KB) via cp.async, 256 threads.
__device__ __forceinline__ void load_blk(uint32_t smem_base, int blk, int tid) {
    const char* s = (const char*)(g_znb + (size_t)blk * 128 * DDIM);
    #pragma unroll
    for (int i = 0; i < 16; ++i) {
        int g   = i * 256 + tid;
        int row = g >> 5;
        int u   = g & 31;
        cp16(smem_base + sw_off(row, u), s + row * 512 + u * 16);
    }
}

// ---------------------------------------------------------------------------
// Kernel 1: normalize -> bf16, scaled by sqrt(10*log2 e)/||z||,
// so bf16 dot = cos * 10 * log2(e) = exp2 argument directly.
// One warp per row (proven config).
// ---------------------------------------------------------------------------
__global__ void normalize_kernel(const float* __restrict__ z_i,
                                 const float* __restrict__ z_j) {
    int row  = blockIdx.x * blockDim.y + threadIdx.y;
    int lane = threadIdx.x;
    const float* src = (row < BHALF) ? (z_i + (size_t)row * DDIM)
                                     : (z_j + (size_t)(row - BHALF) * DDIM);
    const float4* s4 = (const float4*)src;
    float4 v0 = s4[lane];
    float4 v1 = s4[lane + 32];
    float ss = v0.x*v0.x + v0.y*v0.y + v0.z*v0.z + v0.w*v0.w
             + v1.x*v1.x + v1.y*v1.y + v1.z*v1.z + v1.w*v1.w;
    #pragma unroll
    for (int o = 16; o > 0; o >>= 1) ss += __shfl_xor_sync(0xffffffffu, ss, o);
    float scb = 3.7982829f / fmaxf(sqrtf(ss), 1e-8f);   // sqrt(10*log2 e)/||z||

    uint2 b0, b1;
    *(__nv_bfloat162*)&b0.x = __floats2bfloat162_rn(v0.x*scb, v0.y*scb);
    *(__nv_bfloat162*)&b0.y = __floats2bfloat162_rn(v0.z*scb, v0.w*scb);
    *(__nv_bfloat162*)&b1.x = __floats2bfloat162_rn(v1.x*scb, v1.y*scb);
    *(__nv_bfloat162*)&b1.y = __floats2bfloat162_rn(v1.z*scb, v1.w*scb);
    uint2* db = (uint2*)(g_znb + (size_t)row * DDIM);
    db[lane]      = b0;
    db[lane + 32] = b1;
}

// ---------------------------------------------------------------------------
// fold row/col partial sums across the warp and store to g_part for tile
// (tbi, tbj). Writes rs/cs, syncs, then reads.
// ---------------------------------------------------------------------------
__device__ __forceinline__ void fold_store(
    float (&rsum)[2][2], float (&csum)[8][2],
    float (*rs)[128], float (*cs)[128],
    int tbi, int tbj, bool skip_cs,
    int lane, int wx, int wy, int tid)
{
    // row sums: fold (mt, rh) across quad lanes with 3 shfl
    {
        float x0a = (lane & 1) ? rsum[1][0] : rsum[0][0];
        float x0b = (lane & 1) ? rsum[0][0] : rsum[1][0];
        float x0  = x0a + __shfl_xor_sync(0xffffffffu, x0b, 1);
        float x1a = (lane & 1) ? rsum[1][1] : rsum[0][1];
        float x1b = (lane & 1) ? rsum[0][1] : rsum[1][1];
        float x1  = x1a + __shfl_xor_sync(0xffffffffu, x1b, 1);
        float ya  = (lane & 2) ? x1 : x0;
        float yb  = (lane & 2) ? x0 : x1;
        float yr  = ya + __shfl_xor_sync(0xffffffffu, yb, 2);
        rs[wy][wx*32 + (lane&1)*16 + ((lane>>1)&1)*8 + (lane>>2)] = yr;
    }
    // col sums: fold 16 values over 8 row-lanes with 14 shfl
    {
        float z[8];
        #pragma unroll
        for (int nt = 0; nt < 8; ++nt) {
            float c0 = (lane & 4) ? csum[nt][1] : csum[nt][0];
            float d0 = (lane & 4) ? csum[nt][0] : csum[nt][1];
            z[nt] = c0 + __shfl_xor_sync(0xffffffffu, d0, 4);
        }
        float wv[4];
        #pragma unroll
        for (int m = 0; m < 4; ++m) {
            float c0 = (lane & 8) ? z[2*m+1] : z[2*m];
            float d0 = (lane & 8) ? z[2*m]   : z[2*m+1];
            wv[m] = c0 + __shfl_xor_sync(0xffffffffu, d0, 8);
        }
        float u0a = (lane & 16) ? wv[1] : wv[0];
        float u0b = (lane & 16) ? wv[0] : wv[1];
        float u0  = u0a + __shfl_xor_sync(0xffffffffu, u0b, 16);
        float u1a = (lane & 16) ? wv[3] : wv[2];
        float u1b = (lane & 16) ? wv[2] : wv[3];
        float u1  = u1a + __shfl_xor_sync(0xffffffffu, u1b, 16);
        int jp = (lane >> 2) & 1;
        int ntb = ((lane >> 3) & 1) + 2 * ((lane >> 4) & 1);
        cs[wx][wy*64 + ntb*8     + (lane&3)*2 + jp] = u0;
        cs[wx][wy*64 + (ntb+4)*8 + (lane&3)*2 + jp] = u1;
    }
    __syncthreads();
    if (tid < 128) {
        g_part[tbj * NTOT + tbi * 128 + tid] = rs[0][tid] + rs[1][tid];
    } else if (!skip_cs) {
        int c = tid - 128;
        g_part[tbi * NTOT + tbj * 128 + c]
            = (cs[0][c] + cs[1][c]) + (cs[2][c] + cs[3][c]);
    }
}

// ---------------------------------------------------------------------------
// Kernel 2: symmetric bf16 mma.sync GEMM over the upper triangle of the
// 64x64 block grid. Fused epilogue: plain tiles use f16x2 exp2; diag/pos
// tiles use exact f32. 148 CTAs x 14-15 tiles. (Round-10 proven config.)
// ---------------------------------------------------------------------------
__global__ __launch_bounds__(256, 1) void gemm_lse_sym() {
    extern __shared__ __align__(1024) char smem[];
    char* Asm  = smem;
    char* Bsm0 = smem + TILEB;
    char* Bsm1 = smem + 2 * TILEB;
    __shared__ float rs[2][128];
    __shared__ float cs[4][128];

    const int tid  = threadIdx.x;
    const int w    = tid >> 5;
    const int lane = tid & 31;
    const int wx   = w & 3;           // M band (32 rows)
    const int wy   = w >> 2;          // N band (64 cols)

    // ---- tile range (8 CTAs x 15 tiles, 140 x 14) ----
    int t0, cnt;
    if (blockIdx.x < 8) { t0 = blockIdx.x * 15;              cnt = 15; }
    else                { t0 = 120 + (blockIdx.x - 8) * 14;  cnt = 14; }

    int bi = 0, accum = 0;
    while (accum + (NBLK - bi) <= t0) { accum += NBLK - bi; ++bi; }
    int bj = bi + (t0 - accum);

    const uint32_t Abase  = s2u(Asm);
    const uint32_t Bbase0 = s2u(Bsm0);
    const uint32_t Bbase1 = s2u(Bsm1);

    load_blk(Abase, bi, tid);
    uint32_t curB;
    int pb;
    if (bj == bi) { curB = Abase;  pb = 0; }
    else          { load_blk(Bbase0, bj, tid); curB = Bbase0; pb = 1; }
    cp_commit();

    // ldmatrix lane geometry
    const int tile  = lane >> 3;
    const int l7    = lane & 7;
    const int a_row = wx * 32 + (tile & 1) * 8 + l7;
    const int a_kh  = tile >> 1;
    const int b_row = wy * 64 + (tile >> 1) * 8 + l7;
    const int b_kh  = tile & 1;

    for (int it = 0; it < cnt; ++it) {
        const bool have_next = (it + 1 < cnt);
        int nbi = bi, nbj = bj + 1;
        if (nbj == NBLK) { nbi = bi + 1; nbj = nbi; }

        uint32_t nextB = 0;
        if (have_next && nbi == bi) {
            nextB = pb ? Bbase1 : Bbase0;
            load_blk(nextB, nbj, tid);
            cp_commit();
            pb ^= 1;
            cp_wait<1>();
        } else {
            cp_wait<0>();
        }
        __syncthreads();

        // ---- MMA: C = A_bi . B_bj^T (128x128, K=256) ----
        float acc[2][8][4];
        #pragma unroll
        for (int mt = 0; mt < 2; ++mt)
            #pragma unroll
            for (int nt = 0; nt < 8; ++nt)
                #pragma unroll
                for (int j = 0; j < 4; ++j) acc[mt][nt][j] = 0.f;

        #pragma unroll
        for (int ks = 0; ks < 16; ++ks) {
            uint32_t a[2][4];
            #pragma unroll
            for (int mt = 0; mt < 2; ++mt)
                LDSM4(a[mt][0], a[mt][1], a[mt][2], a[mt][3],
                      Abase + sw_off(a_row + mt * 16, ks * 2 + a_kh));
            uint32_t b[8][2];
            #pragma unroll
            for (int np = 0; np < 4; ++np) {
                uint32_t r0, r1, r2, r3;
                LDSM4(r0, r1, r2, r3,
                      curB + sw_off(b_row + np * 16, ks * 2 + b_kh));
                b[2*np][0] = r0;   b[2*np][1] = r1;
                b[2*np+1][0] = r2; b[2*np+1][1] = r3;
            }
            #pragma unroll
            for (int mt = 0; mt < 2; ++mt)
                #pragma unroll
                for (int nt = 0; nt < 8; ++nt)
                    MMA16816(acc[mt][nt], a[mt], b[nt]);
        }

        // ---- epilogue ----
        const bool isdiag = (bi == bj);
        const bool ispos  = (bj == bi + 32);
        float rsum[2][2];
        float csum[8][2];

        if (!isdiag && !ispos) {
            // fast f16x2 path: 2 exps per MUFU op, args shifted by -4
            uint32_t rsum2[2][2] = {{0u,0u},{0u,0u}};
            uint32_t csum2[8] = {0u,0u,0u,0u,0u,0u,0u,0u};
            #pragma unroll
            for (int mt = 0; mt < 2; ++mt)
                #pragma unroll
                for (int nt = 0; nt < 8; ++nt) {
                    uint32_t p01 = pack_h2(acc[mt][nt][0] - 4.f,
                                           acc[mt][nt][1] - 4.f);
                    uint32_t p23 = pack_h2(acc[mt][nt][2] - 4.f,
                                           acc[mt][nt][3] - 4.f);
                    uint32_t e01 = ex2_h2(p01);
                    uint32_t e23 = ex2_h2(p23);
                    hadd2(rsum2[mt][0], e01);
                    hadd2(rsum2[mt][1], e23);
                    hadd2(csum2[nt], e01);
                    hadd2(csum2[nt], e23);
                }
            #pragma unroll
            for (int mt = 0; mt < 2; ++mt)
                #pragma unroll
                for (int rh = 0; rh < 2; ++rh) {
                    float2 f = __half22float2(
                        *reinterpret_cast<__half2*>(&rsum2[mt][rh]));
                    rsum[mt][rh] = (f.x + f.y) * 16.0f;
                }
            #pragma unroll
            for (int nt = 0; nt < 8; ++nt) {
                float2 f = __half22float2(
                    *reinterpret_cast<__half2*>(&csum2[nt]));
                csum[nt][0] = f.x * 16.0f;
                csum[nt][1] = f.y * 16.0f;
            }
        } else {
            // exact f32 path for diagonal / positive tiles
            #pragma unroll
            for (int mt = 0; mt < 2; ++mt)
                #pragma unroll
                for (int rh = 0; rh < 2; ++rh) rsum[mt][rh] = 0.f;
            #pragma unroll
            for (int nt = 0; nt < 8; ++nt)
                csum[nt][0] = csum[nt][1] = 0.f;
            #pragma unroll
            for (int mt = 0; mt < 2; ++mt)
                #pragma unroll
                for (int nt = 0; nt < 8; ++nt)
                    #pragma unroll
                    for (int j = 0; j < 4; ++j) {
                        int lr = wx*32 + (lane>>2) + mt*16 + (j>>1)*8;
                        int lc = wy*64 + nt*8 + (lane&3)*2 + (j&1);
                        float e = ex2(acc[mt][nt][j]);
                        if (lr == lc) {
                            if (ispos)
                                g_pos[bi * 128 + lr] =
                                    0.6931471805599453f * acc[mt][nt][j];
                            else
                                e = 0.f;   // diagonal self-similarity
                        }
                        rsum[mt][j>>1] += e;
                        csum[nt][j&1]  += e;
                    }
        }

        fold_store(rsum, csum, rs, cs, bi, bj, isdiag, lane, wx, wy, tid);
        __syncthreads();   // g_part reads of rs/cs done; MMA done -> A safe

        if (have_next) {
            if (nbi == bi) {
                curB = nextB;
            } else {
                load_blk(Abase, nbi, tid);
                cp_commit();
                curB = Abase;      // next tile is diagonal: B = A
            }
            bi = nbi; bj = nbj;
        }
    }
}

// ---------------------------------------------------------------------------
// Kernel 3: finalize, 4 rows per thread via float4 (coalesced, 4 independent
// accumulator chains). 16 blocks x 128 threads = 2048 threads x 4 rows.
// loss = ln2*log2(p) - g_pos[row mod B]; per-block masked partials; last
// block (threadfence + counter) does the deterministic final mean.
// ---------------------------------------------------------------------------
__global__ __launch_bounds__(128) void finalize_kernel(const int* __restrict__ mask,
                                                       float* __restrict__ out) {
    __shared__ float ssum[128];
    __shared__ float scnt[128];
    __shared__ bool  amLast;
    int tid  = threadIdx.x;
    int r4   = blockIdx.x * 128 + tid;      // float4 index: rows 4*r4..4*r4+3
    int row0 = r4 * 4;

    float4 p = make_float4(0.f, 0.f, 0.f, 0.f);
    const float4* gp = (const float4*)g_part;
    #pragma unroll 8
    for (int t = 0; t < NBLK; ++t) {
        float4 v = gp[t * (NTOT / 4) + r4];
        p.x += v.x; p.y += v.y; p.z += v.z; p.w += v.w;
    }

    const float LN2 = 0.6931471805599453f;
    float ls = 0.f, lc = 0.f;
    #pragma unroll
    for (int j = 0; j < 4; ++j) {
        int row = row0 + j;
        float pv = (j == 0) ? p.x : (j == 1) ? p.y : (j == 2) ? p.z : p.w;
        float loss = LN2 * log2f(pv) - g_pos[row & (BHALF - 1)];
        float m = (mask[row & (BHALF - 1)] != 0) ? 1.0f : 0.0f;
        ls += loss * m;
        lc += m;
    }
    ssum[tid] = ls;
    scnt[tid] = lc;
    __syncthreads();
    #pragma unroll
    for (int s = 64; s > 0; s >>= 1) {
        if (tid < s) { ssum[tid] += ssum[tid + s]; scnt[tid] += scnt[tid + s]; }
        __syncthreads();
    }
    if (tid == 0) {
        g_red[blockIdx.x] = make_float2(ssum[0], scnt[0]);
        __threadfence();
        int t = atomicAdd(&g_count, 1);
        amLast = (t == (int)gridDim.x - 1);
    }
    __syncthreads();

    if (amLast && tid < 16) {
        float2 v = g_red[tid];
        float s = v.x, c = v.y;
        #pragma unroll
        for (int o = 8; o > 0; o >>= 1) {
            s += __shfl_xor_sync(0xffffu, s, o);
            c += __shfl_xor_sync(0xffffu, c, o);
        }
        if (tid == 0) {
            out[0] = (c > 0.0f) ? s / fmaxf(c, 1.0f) : 0.0f;
            g_count = 0;   // reset for next graph replay
        }
    }
}

// ---------------------------------------------------------------------------
extern "C" void kernel_launch(void* const* d_in, const int* in_sizes, int n_in,
                              void* d_out, int out_size) {
    const float* z_i  = (const float*)d_in[0];
    const float* z_j  = (const float*)d_in[1];
    const int*   mask = (const int*)d_in[2];
    float* out = (float*)d_out;
    (void)in_sizes; (void)n_in; (void)out_size;

    cudaFuncSetAttribute(gemm_lse_sym,
                         cudaFuncAttributeMaxDynamicSharedMemorySize,
                         SMEM_TOTAL);

    normalize_kernel<<<NTOT / 8, dim3(32, 8)>>>(z_i, z_j);
    gemm_lse_sym<<<148, 256, SMEM_TOTAL>>>();
    finalize_kernel<<<16, 128>>>(mask, out);
}

// round 16
// speedup vs baseline: 1.0689x; 1.0689x over previous
#include <cuda_runtime.h>
#include <cuda_bf16.h>
#include <cuda_fp16.h>
#include <cstdint>
#include <math.h>

#define NTOT   8192
#define BHALF  4096
#define DDIM   256
#define NBLK   64                 // 128-row blocks
#define TILEB  65536              // 128 rows * 512 B (bf16)
#define SMEM_TOTAL (3 * TILEB)    // A + B0 + B1 = 192 KB

// ---------------- scratch (device globals; allocation-free) ----------------
__device__ __align__(16) __nv_bfloat16 g_znb[NTOT * DDIM]; // bf16 * sqrt(10*log2 e)
__device__ float  g_part[NBLK * NTOT];   // [slot][row] exp2 partial sums
__device__ float  g_pos[BHALF];          // ln-domain positive-pair sims
__device__ float2 g_red[256];            // per-finalize-block (sum, cnt)
__device__ int    g_count;               // finalize completion counter

// ---------------- helpers (baseline PTX only) ----------------
__device__ __forceinline__ uint32_t s2u(const void* p) {
    return (uint32_t)__cvta_generic_to_shared(p);
}
__device__ __forceinline__ void cp16(uint32_t dst, const void* src) {
    asm volatile("cp.async.cg.shared.global [%0], [%1], 16;"
                 :: "r"(dst), "l"(src) : "memory");
}
__device__ __forceinline__ void cp_commit() {
    asm volatile("cp.async.commit_group;" ::: "memory");
}
template <int N> __device__ __forceinline__ void cp_wait() {
    asm volatile("cp.async.wait_group %0;" :: "n"(N) : "memory");
}
__device__ __forceinline__ float ex2(float x) {
    float r;
    asm("ex2.approx.ftz.f32 %0, %1;" : "=f"(r) : "f"(x));
    return r;
}
// pack two f32 into f16x2 (lo = a, hi = b)
__device__ __forceinline__ uint32_t pack_h2(float a, float b) {
    uint32_t r;
    asm("cvt.rn.f16x2.f32 %0, %1, %2;" : "=r"(r) : "f"(b), "f"(a));
    return r;
}
__device__ __forceinline__ uint32_t ex2_h2(uint32_t x) {
    uint32_t r;
    asm("ex2.approx.f16x2 %0, %1;" : "=r"(r) : "r"(x));
    return r;
}
__device__ __forceinline__ void hadd2(uint32_t& acc, uint32_t v) {
    asm("add.rn.f16x2 %0, %0, %1;" : "+r"(acc) : "r"(v));
}
#define LDSM4(r0, r1, r2, r3, addr)                                           \
    asm volatile("ldmatrix.sync.aligned.m8n8.x4.shared.b16 {%0,%1,%2,%3}, [%4];" \
                 : "=r"(r0), "=r"(r1), "=r"(r2), "=r"(r3) : "r"(addr))
#define MMA16816(d, a, b)                                                     \
    asm volatile("mma.sync.aligned.m16n8k16.row.col.f32.bf16.bf16.f32 "       \
                 "{%0,%1,%2,%3},{%4,%5,%6,%7},{%8,%9},{%0,%1,%2,%3};"         \
                 : "+f"((d)[0]), "+f"((d)[1]), "+f"((d)[2]), "+f"((d)[3])     \
                 : "r"((a)[0]), "r"((a)[1]), "r"((a)[2]), "r"((a)[3]),        \
                   "r"((b)[0]), "r"((b)[1]))

// 16B-unit XOR swizzle within a 512B row (32 units/row)
__device__ __forceinline__ uint32_t sw_off(int row, int u) {
    return (uint32_t)((row * 32 + (u ^ (row & 7))) << 4);
}

// Load a 128-row x 512-byte block (64 KB) via cp.async, 256 threads.
__device__ __forceinline__ void load_blk(uint32_t smem_base, int blk, int tid) {
    const char* s = (const char*)(g_znb + (size_t)blk * 128 * DDIM);
    #pragma unroll
    for (int i = 0; i < 16; ++i) {
        int g   = i * 256 + tid;
        int row = g >> 5;
        int u   = g & 31;
        cp16(smem_base + sw_off(row, u), s + row * 512 + u * 16);
    }
}

// ---------------------------------------------------------------------------
// Kernel 1: normalize -> bf16, scaled by sqrt(10*log2 e)/||z||,
// so bf16 dot = cos * 10 * log2(e) = exp2 argument directly.
// ---------------------------------------------------------------------------
__global__ void normalize_kernel(const float* __restrict__ z_i,
                                 const float* __restrict__ z_j) {
    int row  = blockIdx.x * blockDim.y + threadIdx.y;
    int lane = threadIdx.x;
    const float* src = (row < BHALF) ? (z_i + (size_t)row * DDIM)
                                     : (z_j + (size_t)(row - BHALF) * DDIM);
    const float4* s4 = (const float4*)src;
    float4 v0 = s4[lane];
    float4 v1 = s4[lane + 32];
    float ss = v0.x*v0.x + v0.y*v0.y + v0.z*v0.z + v0.w*v0.w
             + v1.x*v1.x + v1.y*v1.y + v1.z*v1.z + v1.w*v1.w;
    #pragma unroll
    for (int o = 16; o > 0; o >>= 1) ss += __shfl_xor_sync(0xffffffffu, ss, o);
    float scb = 3.7982829f / fmaxf(sqrtf(ss), 1e-8f);   // sqrt(10*log2 e)/||z||

    uint2 b0, b1;
    *(__nv_bfloat162*)&b0.x = __floats2bfloat162_rn(v0.x*scb, v0.y*scb);
    *(__nv_bfloat162*)&b0.y = __floats2bfloat162_rn(v0.z*scb, v0.w*scb);
    *(__nv_bfloat162*)&b1.x = __floats2bfloat162_rn(v1.x*scb, v1.y*scb);
    *(__nv_bfloat162*)&b1.y = __floats2bfloat162_rn(v1.z*scb, v1.w*scb);
    uint2* db = (uint2*)(g_znb + (size_t)row * DDIM);
    db[lane]      = b0;
    db[lane + 32] = b1;
}

// ---------------------------------------------------------------------------
// fold row/col partial sums across the warp and store to g_part for tile
// (tbi, tbj). Writes rs/cs, syncs, then reads.
// ---------------------------------------------------------------------------
__device__ __forceinline__ void fold_store(
    float (&rsum)[2][2], float (&csum)[8][2],
    float (*rs)[128], float (*cs)[128],
    int tbi, int tbj, bool skip_cs,
    int lane, int wx, int wy, int tid)
{
    // row sums: fold (mt, rh) across quad lanes with 3 shfl
    {
        float x0a = (lane & 1) ? rsum[1][0] : rsum[0][0];
        float x0b = (lane & 1) ? rsum[0][0] : rsum[1][0];
        float x0  = x0a + __shfl_xor_sync(0xffffffffu, x0b, 1);
        float x1a = (lane & 1) ? rsum[1][1] : rsum[0][1];
        float x1b = (lane & 1) ? rsum[0][1] : rsum[1][1];
        float x1  = x1a + __shfl_xor_sync(0xffffffffu, x1b, 1);
        float ya  = (lane & 2) ? x1 : x0;
        float yb  = (lane & 2) ? x0 : x1;
        float yr  = ya + __shfl_xor_sync(0xffffffffu, yb, 2);
        rs[wy][wx*32 + (lane&1)*16 + ((lane>>1)&1)*8 + (lane>>2)] = yr;
    }
    // col sums: fold 16 values over 8 row-lanes with 14 shfl
    {
        float z[8];
        #pragma unroll
        for (int nt = 0; nt < 8; ++nt) {
            float c0 = (lane & 4) ? csum[nt][1] : csum[nt][0];
            float d0 = (lane & 4) ? csum[nt][0] : csum[nt][1];
            z[nt] = c0 + __shfl_xor_sync(0xffffffffu, d0, 4);
        }
        float wv[4];
        #pragma unroll
        for (int m = 0; m < 4; ++m) {
            float c0 = (lane & 8) ? z[2*m+1] : z[2*m];
            float d0 = (lane & 8) ? z[2*m]   : z[2*m+1];
            wv[m] = c0 + __shfl_xor_sync(0xffffffffu, d0, 8);
        }
        float u0a = (lane & 16) ? wv[1] : wv[0];
        float u0b = (lane & 16) ? wv[0] : wv[1];
        float u0  = u0a + __shfl_xor_sync(0xffffffffu, u0b, 16);
        float u1a = (lane & 16) ? wv[3] : wv[2];
        float u1b = (lane & 16) ? wv[2] : wv[3];
        float u1  = u1a + __shfl_xor_sync(0xffffffffu, u1b, 16);
        int jp = (lane >> 2) & 1;
        int ntb = ((lane >> 3) & 1) + 2 * ((lane >> 4) & 1);
        cs[wx][wy*64 + ntb*8     + (lane&3)*2 + jp] = u0;
        cs[wx][wy*64 + (ntb+4)*8 + (lane&3)*2 + jp] = u1;
    }
    __syncthreads();
    if (tid < 128) {
        g_part[tbj * NTOT + tbi * 128 + tid] = rs[0][tid] + rs[1][tid];
    } else if (!skip_cs) {
        int c = tid - 128;
        g_part[tbi * NTOT + tbj * 128 + c]
            = (cs[0][c] + cs[1][c]) + (cs[2][c] + cs[3][c]);
    }
}

// ---------------------------------------------------------------------------
// Kernel 2: symmetric bf16 mma.sync GEMM over the upper triangle of the
// 64x64 block grid. Fused epilogue: plain tiles use f16x2 exp2 (2 exps per
// MUFU op, shifted by -4 and rescaled x16); diag/pos tiles use exact f32.
// 148 CTAs x 14-15 tiles.
// ---------------------------------------------------------------------------
__global__ __launch_bounds__(256, 1) void gemm_lse_sym() {
    extern __shared__ __align__(1024) char smem[];
    char* Asm  = smem;
    char* Bsm0 = smem + TILEB;
    char* Bsm1 = smem + 2 * TILEB;
    __shared__ float rs[2][128];
    __shared__ float cs[4][128];

    const int tid  = threadIdx.x;
    const int w    = tid >> 5;
    const int lane = tid & 31;
    const int wx   = w & 3;           // M band (32 rows)
    const int wy   = w >> 2;          // N band (64 cols)

    // ---- tile range (8 CTAs x 15 tiles, 140 x 14) ----
    int t0, cnt;
    if (blockIdx.x < 8) { t0 = blockIdx.x * 15;              cnt = 15; }
    else                { t0 = 120 + (blockIdx.x - 8) * 14;  cnt = 14; }

    int bi = 0, accum = 0;
    while (accum + (NBLK - bi) <= t0) { accum += NBLK - bi; ++bi; }
    int bj = bi + (t0 - accum);

    const uint32_t Abase  = s2u(Asm);
    const uint32_t Bbase0 = s2u(Bsm0);
    const uint32_t Bbase1 = s2u(Bsm1);

    load_blk(Abase, bi, tid);
    uint32_t curB;
    int pb;
    if (bj == bi) { curB = Abase;  pb = 0; }
    else          { load_blk(Bbase0, bj, tid); curB = Bbase0; pb = 1; }
    cp_commit();

    // ldmatrix lane geometry
    const int tile  = lane >> 3;
    const int l7    = lane & 7;
    const int a_row = wx * 32 + (tile & 1) * 8 + l7;
    const int a_kh  = tile >> 1;
    const int b_row = wy * 64 + (tile >> 1) * 8 + l7;
    const int b_kh  = tile & 1;

    for (int it = 0; it < cnt; ++it) {
        const bool have_next = (it + 1 < cnt);
        int nbi = bi, nbj = bj + 1;
        if (nbj == NBLK) { nbi = bi + 1; nbj = nbi; }

        uint32_t nextB = 0;
        if (have_next && nbi == bi) {
            nextB = pb ? Bbase1 : Bbase0;
            load_blk(nextB, nbj, tid);
            cp_commit();
            pb ^= 1;
            cp_wait<1>();
        } else {
            cp_wait<0>();
        }
        __syncthreads();

        // ---- MMA: C = A_bi . B_bj^T (128x128, K=256) ----
        float acc[2][8][4];
        #pragma unroll
        for (int mt = 0; mt < 2; ++mt)
            #pragma unroll
            for (int nt = 0; nt < 8; ++nt)
                #pragma unroll
                for (int j = 0; j < 4; ++j) acc[mt][nt][j] = 0.f;

        #pragma unroll
        for (int ks = 0; ks < 16; ++ks) {
            uint32_t a[2][4];
            #pragma unroll
            for (int mt = 0; mt < 2; ++mt)
                LDSM4(a[mt][0], a[mt][1], a[mt][2], a[mt][3],
                      Abase + sw_off(a_row + mt * 16, ks * 2 + a_kh));
            uint32_t b[8][2];
            #pragma unroll
            for (int np = 0; np < 4; ++np) {
                uint32_t r0, r1, r2, r3;
                LDSM4(r0, r1, r2, r3,
                      curB + sw_off(b_row + np * 16, ks * 2 + b_kh));
                b[2*np][0] = r0;   b[2*np][1] = r1;
                b[2*np+1][0] = r2; b[2*np+1][1] = r3;
            }
            #pragma unroll
            for (int mt = 0; mt < 2; ++mt)
                #pragma unroll
                for (int nt = 0; nt < 8; ++nt)
                    MMA16816(acc[mt][nt], a[mt], b[nt]);
        }

        // ---- epilogue ----
        const bool isdiag = (bi == bj);
        const bool ispos  = (bj == bi + 32);
        float rsum[2][2];
        float csum[8][2];

        if (!isdiag && !ispos) {
            // fast f16x2 path: 2 exps per MUFU op, args shifted by -4
            uint32_t rsum2[2][2] = {{0u,0u},{0u,0u}};
            uint32_t csum2[8] = {0u,0u,0u,0u,0u,0u,0u,0u};
            #pragma unroll
            for (int mt = 0; mt < 2; ++mt)
                #pragma unroll
                for (int nt = 0; nt < 8; ++nt) {
                    uint32_t p01 = pack_h2(acc[mt][nt][0] - 4.f,
                                           acc[mt][nt][1] - 4.f);
                    uint32_t p23 = pack_h2(acc[mt][nt][2] - 4.f,
                                           acc[mt][nt][3] - 4.f);
                    uint32_t e01 = ex2_h2(p01);
                    uint32_t e23 = ex2_h2(p23);
                    hadd2(rsum2[mt][0], e01);
                    hadd2(rsum2[mt][1], e23);
                    hadd2(csum2[nt], e01);
                    hadd2(csum2[nt], e23);
                }
            #pragma unroll
            for (int mt = 0; mt < 2; ++mt)
                #pragma unroll
                for (int rh = 0; rh < 2; ++rh) {
                    float2 f = __half22float2(
                        *reinterpret_cast<__half2*>(&rsum2[mt][rh]));
                    rsum[mt][rh] = (f.x + f.y) * 16.0f;
                }
            #pragma unroll
            for (int nt = 0; nt < 8; ++nt) {
                float2 f = __half22float2(
                    *reinterpret_cast<__half2*>(&csum2[nt]));
                csum[nt][0] = f.x * 16.0f;
                csum[nt][1] = f.y * 16.0f;
            }
        } else {
            // exact f32 path for diagonal / positive tiles
            #pragma unroll
            for (int mt = 0; mt < 2; ++mt)
                #pragma unroll
                for (int rh = 0; rh < 2; ++rh) rsum[mt][rh] = 0.f;
            #pragma unroll
            for (int nt = 0; nt < 8; ++nt)
                csum[nt][0] = csum[nt][1] = 0.f;
            #pragma unroll
            for (int mt = 0; mt < 2; ++mt)
                #pragma unroll
                for (int nt = 0; nt < 8; ++nt)
                    #pragma unroll
                    for (int j = 0; j < 4; ++j) {
                        int lr = wx*32 + (lane>>2) + mt*16 + (j>>1)*8;
                        int lc = wy*64 + nt*8 + (lane&3)*2 + (j&1);
                        float e = ex2(acc[mt][nt][j]);
                        if (lr == lc) {
                            if (ispos)
                                g_pos[bi * 128 + lr] =
                                    0.6931471805599453f * acc[mt][nt][j];
                            else
                                e = 0.f;   // diagonal self-similarity
                        }
                        rsum[mt][j>>1] += e;
                        csum[nt][j&1]  += e;
                    }
        }

        fold_store(rsum, csum, rs, cs, bi, bj, isdiag, lane, wx, wy, tid);
        __syncthreads();   // g_part reads of rs/cs done; MMA done -> A safe

        if (have_next) {
            if (nbi == bi) {
                curB = nextB;
            } else {
                load_blk(Abase, nbi, tid);
                cp_commit();
                curB = Abase;      // next tile is diagonal: B = A
            }
            bi = nbi; bj = nbj;
        }
    }
}

// ---------------------------------------------------------------------------
// Kernel 3: loss_k = ln2*log2(sum_t g_part[t][k]) - g_pos[k mod B],
// masked per-block partials, then LAST block does the deterministic final
// mean (threadfence + atomic counter). 256 blocks x (32,32).
// ---------------------------------------------------------------------------
__global__ __launch_bounds__(1024) void finalize_kernel(const int* __restrict__ mask,
                                                        float* __restrict__ out) {
    __shared__ float2 wres[32];
    __shared__ float2 sh2[8];
    __shared__ bool   amLast;
    int lane = threadIdx.x;
    int wy   = threadIdx.y;
    int ftid = wy * 32 + lane;
    int row  = blockIdx.x * 32 + wy;

    float p = g_part[lane * NTOT + row] + g_part[(lane + 32) * NTOT + row];
    #pragma unroll
    for (int o = 16; o > 0; o >>= 1)
        p += __shfl_xor_sync(0xffffffffu, p, o);

    if (lane == 0) {
        float loss = 0.6931471805599453f * log2f(p) - g_pos[row & (BHALF - 1)];
        float m = (mask[row & (BHALF - 1)] != 0) ? 1.0f : 0.0f;
        wres[wy] = make_float2(loss * m, m);
    }
    __syncthreads();
    if (wy == 0) {
        float2 v = wres[lane];
        float s = v.x, c = v.y;
        #pragma unroll
        for (int o = 16; o > 0; o >>= 1) {
            s += __shfl_xor_sync(0xffffffffu, s, o);
            c += __shfl_xor_sync(0xffffffffu, c, o);
        }
        if (lane == 0) {
            g_red[blockIdx.x] = make_float2(s, c);
            __threadfence();
            int t = atomicAdd(&g_count, 1);
            amLast = (t == (int)gridDim.x - 1);
        }
    }
    __syncthreads();

    if (amLast) {
        if (ftid < 256) {
            float2 v = g_red[ftid];
            float s = v.x, c = v.y;
            #pragma unroll
            for (int o = 16; o > 0; o >>= 1) {
                s += __shfl_xor_sync(0xffffffffu, s, o);
                c += __shfl_xor_sync(0xffffffffu, c, o);
            }
            if ((ftid & 31) == 0) sh2[ftid >> 5] = make_float2(s, c);
        }
        __syncthreads();
        if (ftid == 0) {
            float S = 0.f, C = 0.f;
            #pragma unroll
            for (int i = 0; i < 8; ++i) { S += sh2[i].x; C += sh2[i].y; }
            out[0] = (C > 0.0f) ? S / fmaxf(C, 1.0f) : 0.0f;
            g_count = 0;   // reset for next graph replay
        }
    }
}

// ---------------------------------------------------------------------------
extern "C" void kernel_launch(void* const* d_in, const int* in_sizes, int n_in,
                              void* d_out, int out_size) {
    const float* z_i  = (const float*)d_in[0];
    const float* z_j  = (const float*)d_in[1];
    const int*   mask = (const int*)d_in[2];
    float* out = (float*)d_out;
    (void)in_sizes; (void)n_in; (void)out_size;

    cudaFuncSetAttribute(gemm_lse_sym,
                         cudaFuncAttributeMaxDynamicSharedMemorySize,
                         SMEM_TOTAL);

    normalize_kernel<<<NTOT / 8, dim3(32, 8)>>>(z_i, z_j);
    gemm_lse_sym<<<148, 256, SMEM_TOTAL>>>();
    finalize_kernel<<<256, dim3(32, 32)>>>(mask, out);
}